// round 14
// baseline (speedup 1.0000x reference)
#include <cuda_runtime.h>
#include <cstdint>
#include <cstddef>

#define D 128
#define NVEC 65536                 // 16 * 64 * 64
#define OUT_TENSOR 67108864LL      // 8*16*128*64*64

// -------- scratch (static device globals; no runtime allocation) --------
__device__ uint8_t g_idxb[8 * NVEC];   // level-major byte indices
__device__ float   g_part[256 * 8];    // per-CTA loss partials

// stage -> SLOT indices into the packed 10 distinct rows (c_rl order)
__constant__ int c_st[16]   = {0,1, 2,3, 3,4, 4,5, 5,6, 6,7, 7,8, 8,9};
__constant__ int c_rl[10]   = {0, 1, 3, 4, 5, 6, 7, 8, 9, 10};   // distinct rows
__constant__ float c_coef[8] = {1.5f, 1.2f, 1.0f, 0.9f, 0.82f, 0.69f, 0.65f, 0.56f};
// upper-triangular pair list for the 10x10 gram matrix (slot indices)
__constant__ unsigned char c_pi[55] = {0,0,0,0,0,0,0,0,0,0, 1,1,1,1,1,1,1,1,1,
                                       2,2,2,2,2,2,2,2, 3,3,3,3,3,3,3, 4,4,4,4,4,4,
                                       5,5,5,5,5, 6,6,6,6, 7,7,7, 8,8, 9};
__constant__ unsigned char c_pj[55] = {0,1,2,3,4,5,6,7,8,9, 1,2,3,4,5,6,7,8,9,
                                       2,3,4,5,6,7,8,9, 3,4,5,6,7,8,9, 4,5,6,7,8,9,
                                       5,6,7,8,9, 6,7,8,9, 7,8,9, 8,9, 9};

// ---------------------------------------------------------------------------
// Kernel 1: per-vector quantization. 256 CTAs x 256 threads (occ 2, ~1 wave).
// Plain float4/FFMA dot core over the 10 distinct rows (NO inline asm).
// Norms via bit-path recurrence over the in-CTA 10x10 Gram.
// Exact strict-< argmin (validated rel_err ~7e-8).
// ---------------------------------------------------------------------------
__global__ void __launch_bounds__(256, 2)
quant_kernel(const float* __restrict__ inp, const float* __restrict__ w) {
    __shared__ __align__(16) float s_bv[10][128];    // 10 distinct rows *(-2)
    __shared__ float sG[100];                        // gram of scaled rows (= 4 * true gram)
    __shared__ float sC[768];                        // padded codeword norms
    __shared__ float s_loss[8];

    int tid = threadIdx.x, wid = tid >> 5, lane = tid & 31;

    for (int i = tid; i < 1280; i += 256) {
        int t = i >> 7, c = i & 127;
        s_bv[t][c] = -2.0f * w[c_rl[t] * D + c];
    }
    if (tid < 8) s_loss[tid] = 0.f;
    __syncthreads();

    // gram over SLOTS (55 pairs across 8 warps); conflict-free LDS
    for (int p = wid; p < 55; p += 8) {
        int i = c_pi[p], j = c_pj[p];
        float s = 0.f;
        #pragma unroll
        for (int cc = 0; cc < 4; cc++)
            s = fmaf(s_bv[i][lane + 32 * cc], s_bv[j][lane + 32 * cc], s);
        #pragma unroll
        for (int o = 16; o; o >>= 1) s += __shfl_xor_sync(0xffffffffu, s, o);
        if (lane == 0) { sG[i * 10 + j] = s; sG[j * 10 + i] = s; }
    }
    __syncthreads();

    // codeword norms via per-thread bit-path recurrence (256 threads = 256 paths)
    {
        const int padv[8] = {0, 4, 8, 16, 48, 112, 240, 496};
        int u[8];
        #pragma unroll
        for (int l = 1; l <= 8; l++) {
            int bit = (tid >> (8 - l)) & 1;
            u[l - 1] = (l == 1) ? bit : (l + bit);
        }
        float M = 0.f;
        #pragma unroll
        for (int l = 1; l <= 8; l++) {
            float cross = 0.f;
            #pragma unroll
            for (int s = 0; s < l - 1; s++) cross += sG[u[s] * 10 + u[l - 1]];
            M += 2.f * cross + sG[u[l - 1] * 10 + u[l - 1]];
            if ((tid & ((1 << (8 - l)) - 1)) == 0)
                sC[padv[l - 1] + (tid >> (8 - l))] = 0.25f * M;
        }
    }
    __syncthreads();

    int vec = blockIdx.x * 256 + tid;                     // 0..65535
    const float* xp = inp + ((size_t)(vec >> 12) << 19) + (vec & 4095);
    const float4* sb4 = reinterpret_cast<const float4*>(&s_bv[0][0]);  // [t*32 + c4]

    float acc[10];
    #pragma unroll
    for (int t = 0; t < 10; t++) acc[t] = 0.f;
    float xn = 0.f;

    #pragma unroll 4
    for (int c4 = 0; c4 < 32; c4++) {
        float x0 = xp[(4 * c4 + 0) * 4096];
        float x1 = xp[(4 * c4 + 1) * 4096];
        float x2 = xp[(4 * c4 + 2) * 4096];
        float x3 = xp[(4 * c4 + 3) * 4096];
        xn = fmaf(x0, x0, xn); xn = fmaf(x1, x1, xn);
        xn = fmaf(x2, x2, xn); xn = fmaf(x3, x3, xn);
        #pragma unroll
        for (int t = 0; t < 10; t++) {
            float4 b = sb4[t * 32 + c4];
            acc[t] = fmaf(x0, b.x, acc[t]);
            acc[t] = fmaf(x1, b.y, acc[t]);
            acc[t] = fmaf(x2, b.z, acc[t]);
            acc[t] = fmaf(x3, b.w, acc[t]);
        }
    }

    // p[2s+b] = -2 x . v_{s,b}  (stage slots: (0,1)(2,3)(3,4)(4,5)(5,6)(6,7)(7,8)(8,9))
    float p[16] = {acc[0], acc[1], acc[2], acc[3], acc[3], acc[4], acc[4], acc[5],
                   acc[5], acc[6], acc[6], acc[7], acc[7], acc[8], acc[8], acc[9]};

    float A2[4], A3[8], A4[16], B2[4], B3[8], B4[16];
    #pragma unroll
    for (int j = 0; j < 4;  j++) A2[j] = p[j >> 1] + p[2 + (j & 1)];
    #pragma unroll
    for (int j = 0; j < 8;  j++) A3[j] = A2[j >> 1] + p[4 + (j & 1)];
    #pragma unroll
    for (int j = 0; j < 16; j++) A4[j] = A3[j >> 1] + p[6 + (j & 1)];
    #pragma unroll
    for (int j = 0; j < 4;  j++) B2[j] = p[8 + (j >> 1)] + p[10 + (j & 1)];
    #pragma unroll
    for (int j = 0; j < 8;  j++) B3[j] = B2[j >> 1] + p[12 + (j & 1)];
    #pragma unroll
    for (int j = 0; j < 16; j++) B4[j] = B3[j >> 1] + p[14 + (j & 1)];

    const float INF = __int_as_float(0x7f800000);
    float m[8]; int mi[8];
    #pragma unroll
    for (int l = 0; l < 8; l++) { m[l] = INF; mi[l] = 0; }

    // strict '<' keeps the FIRST minimum (matches jnp.argmin tie-break)
    #pragma unroll
    for (int j = 0; j < 2;   j++) { float s = p[j]            + sC[0   + j]; if (s < m[0]) { m[0] = s; mi[0] = j; } }
    #pragma unroll
    for (int j = 0; j < 4;   j++) { float s = A2[j]           + sC[4   + j]; if (s < m[1]) { m[1] = s; mi[1] = j; } }
    #pragma unroll
    for (int j = 0; j < 8;   j++) { float s = A3[j]           + sC[8   + j]; if (s < m[2]) { m[2] = s; mi[2] = j; } }
    #pragma unroll
    for (int j = 0; j < 16;  j++) { float s = A4[j]           + sC[16  + j]; if (s < m[3]) { m[3] = s; mi[3] = j; } }
    #pragma unroll
    for (int j = 0; j < 32;  j++) { float s = A4[j >> 1] + p[8 + (j & 1)]  + sC[48  + j]; if (s < m[4]) { m[4] = s; mi[4] = j; } }
    #pragma unroll
    for (int j = 0; j < 64;  j++) { float s = A4[j >> 2] + B2[j & 3]       + sC[112 + j]; if (s < m[5]) { m[5] = s; mi[5] = j; } }
    #pragma unroll
    for (int j = 0; j < 128; j++) { float s = A4[j >> 3] + B3[j & 7]       + sC[240 + j]; if (s < m[6]) { m[6] = s; mi[6] = j; } }
    #pragma unroll
    for (int j = 0; j < 256; j++) { float s = A4[j >> 4] + B4[j & 15]      + sC[496 + j]; if (s < m[7]) { m[7] = s; mi[7] = j; } }

    // level-major byte indices (coalesced per level)
    #pragma unroll
    for (int l = 0; l < 8; l++) g_idxb[(l << 16) + vec] = (uint8_t)mi[l];

    #pragma unroll
    for (int l = 0; l < 8; l++) {
        float v = xn + m[l];
        #pragma unroll
        for (int o = 16; o; o >>= 1) v += __shfl_xor_sync(0xffffffffu, v, o);
        if (lane == 0) atomicAdd(&s_loss[l], v);
    }
    __syncthreads();
    if (tid < 8) g_part[blockIdx.x * 8 + tid] = s_loss[tid];
}

// ---------------------------------------------------------------------------
// Kernel 2: output writer (R7/R11 body — 46.3 us measured). 512 CTAs =
// (8 levels x 16 batches x 4 channel-quarters), heavy levels first, occ 5.
// In-CTA codebook build for its 32 channels, scalar gather, STG.128.
// ---------------------------------------------------------------------------
__global__ void __launch_bounds__(256, 5)
scatter_kernel(const float* __restrict__ w, float* __restrict__ out) {
    __shared__ float    scb[8192];     // 32 channels x sz (<=256)
    __shared__ float    srow[320];     // 10 slots x 32 channels
    __shared__ uint32_t sidx[1024];    // 4096 byte-indices
    __shared__ int      sst[16];

    int bid   = blockIdx.x;
    int level = 7 - (bid >> 6);        // heavy levels first
    int r     = bid & 63;
    int b     = r >> 2;                // 0..15
    int q     = r & 3;                 // channel quarter
    int L     = level + 1;
    int sz    = 2 << level;
    int tid   = threadIdx.x;

    if (tid < 16) sst[tid] = c_st[tid];
    for (int i = tid; i < 320; i += 256)
        srow[i] = w[c_rl[i >> 5] * D + q * 32 + (i & 31)];
    {
        const uint4* src = reinterpret_cast<const uint4*>(
            g_idxb + ((size_t)level << 16) + ((size_t)b << 12));
        reinterpret_cast<uint4*>(sidx)[tid] = src[tid];
    }
    __syncthreads();

    // build codebook slice: scb[cl*sz + j], cl = local channel 0..31
    int n = sz << 5;
    for (int u = tid; u < n; u += 256) {
        int cl = u >> L;
        int j  = u & (sz - 1);
        float v = 0.f;
        #pragma unroll 8
        for (int s = 0; s < L; s++) {
            int bit = (j >> (L - 1 - s)) & 1;
            v += srow[sst[2 * s + bit] * 32 + cl];
        }
        scb[u] = v;
    }
    __syncthreads();

    // loss finalize (one CTA; quant complete by stream order)
    if (bid == 0) {
        int l = tid >> 5, ln = tid & 31;
        float s = 0.f;
        #pragma unroll
        for (int k = 0; k < 8; k++) s += g_part[(ln + 32 * k) * 8 + l];
        #pragma unroll
        for (int o = 16; o; o >>= 1) s += __shfl_xor_sync(0xffffffffu, s, o);
        if (ln == 0)
            out[OUT_TENSOR + l] = (c_coef[l] + 0.4f) * s * (1.0f / 8388608.0f);
    }

    // per-thread indices: quad g covers hw = g*1024 + 4*tid .. +3
    int o[16];
    #pragma unroll
    for (int g = 0; g < 4; g++) {
        uint32_t u = sidx[g * 256 + tid];
        o[4 * g + 0] =  u        & 255;
        o[4 * g + 1] = (u >> 8)  & 255;
        o[4 * g + 2] = (u >> 16) & 255;
        o[4 * g + 3] =  u >> 24;
    }

    // out index = ((level*16 + b)*128 + q*32 + cl) * 4096 + hw
    float* ob = out + ((((size_t)((level << 4) + b) << 7) + ((size_t)(q << 5))) << 12)
                    + (tid << 2);
    const float* row = scb;
    for (int cl = 0; cl < 32; cl++) {
        #pragma unroll
        for (int g = 0; g < 4; g++) {
            float4 v = make_float4(row[o[4 * g + 0]], row[o[4 * g + 1]],
                                   row[o[4 * g + 2]], row[o[4 * g + 3]]);
            *reinterpret_cast<float4*>(ob + g * 1024) = v;
        }
        row += sz;
        ob  += 4096;
    }
}

// ---------------------------------------------------------------------------
extern "C" void kernel_launch(void* const* d_in, const int* in_sizes, int n_in,
                              void* d_out, int out_size) {
    const float* inp = (const float*)d_in[0];   // (16,128,64,64) f32
    const float* w   = (const float*)d_in[1];   // (256,128) f32
    float* out       = (float*)d_out;

    (void)in_sizes; (void)n_in; (void)out_size;

    quant_kernel<<<256, 256>>>(inp, w);
    scatter_kernel<<<512, 256>>>(w, out);
}

// round 15
// speedup vs baseline: 1.3105x; 1.3105x over previous
#include <cuda_runtime.h>
#include <cstdint>
#include <cstddef>

#define D 128
#define NVEC 65536                 // 16 * 64 * 64
#define OUT_TENSOR 67108864LL      // 8*16*128*64*64

// -------- scratch (static device globals; no runtime allocation) --------
__device__ unsigned long long g_idx[NVEC];   // 8 packed uint8 indices per vector
__device__ float g_cnorm[768];               // ||c||^2, padded per level
__device__ float g_part[256 * 8];            // per-CTA loss partials

// stage s (0-based) uses weight rows c_rows[2s], c_rows[2s+1]
__constant__ int c_rows[16] = {0,1, 3,4, 4,5, 5,6, 6,7, 7,8, 8,9, 9,10};
// stage -> SLOT indices into the packed 10 distinct rows (c_rl order)
__constant__ int c_st[16]   = {0,1, 2,3, 3,4, 4,5, 5,6, 6,7, 7,8, 8,9};
__constant__ int c_rl[10]   = {0, 1, 3, 4, 5, 6, 7, 8, 9, 10};   // distinct rows
__constant__ int c_pad[8]   = {0, 4, 8, 16, 48, 112, 240, 496};
__constant__ float c_coef[8] = {1.5f, 1.2f, 1.0f, 0.9f, 0.82f, 0.69f, 0.65f, 0.56f};

// ---------------------------------------------------------------------------
// Kernel 0: codeword norms. One block per codeword (510 x 128), shuffle
// reduction (measured 5.7-6.6 us).
// ---------------------------------------------------------------------------
__global__ void build_kernel(const float* __restrict__ w) {
    int k  = blockIdx.x;              // 0..509 global codeword id
    int li = 30 - __clz(k + 2);       // level index 0..7
    int L  = li + 1;
    int sz = 1 << L;
    int j  = k - (sz - 2);            // codeword index within level
    int c  = threadIdx.x;             // channel 0..127

    float val = 0.f;
    #pragma unroll 8
    for (int s = 0; s < L; s++) {
        int bit = (j >> (L - 1 - s)) & 1;
        val += w[c_rows[2 * s + bit] * D + c];
    }

    float v2 = val * val;
    #pragma unroll
    for (int o = 16; o; o >>= 1) v2 += __shfl_xor_sync(0xffffffffu, v2, o);
    __shared__ float part[4];
    if ((c & 31) == 0) part[c >> 5] = v2;
    __syncthreads();
    if (c == 0) g_cnorm[c_pad[li] + j] = part[0] + part[1] + part[2] + part[3];
}

// ---------------------------------------------------------------------------
// Kernel 1: per-vector quantization. 256 CTAs x 256 threads (occ 2, 1 wave).
// Plain float4/FFMA core over the 10 distinct rows; norms from g_cnorm;
// exact strict-< argmin; ONE packed u64 index store per vector.
// ---------------------------------------------------------------------------
__global__ void __launch_bounds__(256, 2)
quant_kernel(const float* __restrict__ inp, const float* __restrict__ w) {
    __shared__ __align__(16) float s_bv[10][128];    // 10 distinct rows *(-2)
    __shared__ float sC[768];                        // padded codeword norms
    __shared__ float s_loss[8];

    int tid = threadIdx.x, lane = tid & 31;

    for (int i = tid; i < 1280; i += 256) {
        int t = i >> 7, c = i & 127;
        s_bv[t][c] = -2.0f * w[c_rl[t] * D + c];
    }
    for (int i = tid; i < 752; i += 256) sC[i] = g_cnorm[i];
    if (tid < 8) s_loss[tid] = 0.f;
    __syncthreads();

    int vec = blockIdx.x * 256 + tid;                     // 0..65535
    const float* xp = inp + ((size_t)(vec >> 12) << 19) + (vec & 4095);
    const float4* sb4 = reinterpret_cast<const float4*>(&s_bv[0][0]);  // [t*32 + c4]

    float acc[10];
    #pragma unroll
    for (int t = 0; t < 10; t++) acc[t] = 0.f;
    float xn = 0.f;

    #pragma unroll 4
    for (int c4 = 0; c4 < 32; c4++) {
        float x0 = xp[(4 * c4 + 0) * 4096];
        float x1 = xp[(4 * c4 + 1) * 4096];
        float x2 = xp[(4 * c4 + 2) * 4096];
        float x3 = xp[(4 * c4 + 3) * 4096];
        xn = fmaf(x0, x0, xn); xn = fmaf(x1, x1, xn);
        xn = fmaf(x2, x2, xn); xn = fmaf(x3, x3, xn);
        #pragma unroll
        for (int t = 0; t < 10; t++) {
            float4 b = sb4[t * 32 + c4];
            acc[t] = fmaf(x0, b.x, acc[t]);
            acc[t] = fmaf(x1, b.y, acc[t]);
            acc[t] = fmaf(x2, b.z, acc[t]);
            acc[t] = fmaf(x3, b.w, acc[t]);
        }
    }

    // p[2s+b] = -2 x . v_{s,b}  (stage slots: (0,1)(2,3)(3,4)(4,5)(5,6)(6,7)(7,8)(8,9))
    float p[16] = {acc[0], acc[1], acc[2], acc[3], acc[3], acc[4], acc[4], acc[5],
                   acc[5], acc[6], acc[6], acc[7], acc[7], acc[8], acc[8], acc[9]};

    float A2[4], A3[8], A4[16], B2[4], B3[8], B4[16];
    #pragma unroll
    for (int j = 0; j < 4;  j++) A2[j] = p[j >> 1] + p[2 + (j & 1)];
    #pragma unroll
    for (int j = 0; j < 8;  j++) A3[j] = A2[j >> 1] + p[4 + (j & 1)];
    #pragma unroll
    for (int j = 0; j < 16; j++) A4[j] = A3[j >> 1] + p[6 + (j & 1)];
    #pragma unroll
    for (int j = 0; j < 4;  j++) B2[j] = p[8 + (j >> 1)] + p[10 + (j & 1)];
    #pragma unroll
    for (int j = 0; j < 8;  j++) B3[j] = B2[j >> 1] + p[12 + (j & 1)];
    #pragma unroll
    for (int j = 0; j < 16; j++) B4[j] = B3[j >> 1] + p[14 + (j & 1)];

    const float INF = __int_as_float(0x7f800000);
    float m[8]; int mi[8];
    #pragma unroll
    for (int l = 0; l < 8; l++) { m[l] = INF; mi[l] = 0; }

    // strict '<' keeps the FIRST minimum (matches jnp.argmin tie-break)
    #pragma unroll
    for (int j = 0; j < 2;   j++) { float s = p[j]            + sC[0   + j]; if (s < m[0]) { m[0] = s; mi[0] = j; } }
    #pragma unroll
    for (int j = 0; j < 4;   j++) { float s = A2[j]           + sC[4   + j]; if (s < m[1]) { m[1] = s; mi[1] = j; } }
    #pragma unroll
    for (int j = 0; j < 8;   j++) { float s = A3[j]           + sC[8   + j]; if (s < m[2]) { m[2] = s; mi[2] = j; } }
    #pragma unroll
    for (int j = 0; j < 16;  j++) { float s = A4[j]           + sC[16  + j]; if (s < m[3]) { m[3] = s; mi[3] = j; } }
    #pragma unroll
    for (int j = 0; j < 32;  j++) { float s = A4[j >> 1] + p[8 + (j & 1)]  + sC[48  + j]; if (s < m[4]) { m[4] = s; mi[4] = j; } }
    #pragma unroll
    for (int j = 0; j < 64;  j++) { float s = A4[j >> 2] + B2[j & 3]       + sC[112 + j]; if (s < m[5]) { m[5] = s; mi[5] = j; } }
    #pragma unroll
    for (int j = 0; j < 128; j++) { float s = A4[j >> 3] + B3[j & 7]       + sC[240 + j]; if (s < m[6]) { m[6] = s; mi[6] = j; } }
    #pragma unroll
    for (int j = 0; j < 256; j++) { float s = A4[j >> 4] + B4[j & 15]      + sC[496 + j]; if (s < m[7]) { m[7] = s; mi[7] = j; } }

    // single packed u64 index store (R1 behavior)
    unsigned long long pk = 0;
    #pragma unroll
    for (int l = 0; l < 8; l++) pk |= ((unsigned long long)(unsigned)mi[l]) << (8 * l);
    g_idx[vec] = pk;

    #pragma unroll
    for (int l = 0; l < 8; l++) {
        float v = xn + m[l];
        #pragma unroll
        for (int o = 16; o; o >>= 1) v += __shfl_xor_sync(0xffffffffu, v, o);
        if (lane == 0) atomicAdd(&s_loss[l], v);
    }
    __syncthreads();
    if (tid < 8) g_part[blockIdx.x * 8 + tid] = s_loss[tid];
}

// ---------------------------------------------------------------------------
// Kernel 2: output writer (512-tile occ-5 body, measured 46-49 us). 512 CTAs
// = (8 levels x 16 batches x 4 channel-quarters), heavy levels first.
// In-CTA codebook build for its 32 channels, scalar gather, STG.128,
// plus loss finalize in CTA 0.
// ---------------------------------------------------------------------------
__global__ void __launch_bounds__(256, 5)
scatter_kernel(const float* __restrict__ w, float* __restrict__ out) {
    __shared__ float    scb[8192];     // 32 channels x sz (<=256)
    __shared__ float    srow[320];     // 10 slots x 32 channels
    __shared__ uint32_t sidx[1024];    // 4096 byte-indices
    __shared__ int      sst[16];

    int bid   = blockIdx.x;
    int level = 7 - (bid >> 6);        // heavy levels first
    int r     = bid & 63;
    int b     = r >> 2;                // 0..15
    int q     = r & 3;                 // channel quarter
    int L     = level + 1;
    int sz    = 2 << level;
    int tid   = threadIdx.x;

    if (tid < 16) sst[tid] = c_st[tid];
    for (int i = tid; i < 320; i += 256)
        srow[i] = w[c_rl[i >> 5] * D + q * 32 + (i & 31)];
    {
        // unpack this level's byte from the packed u64 indices
        const unsigned long long* gi = g_idx + ((size_t)b << 12);
        int sh = level << 3;
        uint8_t* s8 = reinterpret_cast<uint8_t*>(sidx);
        for (int i = tid; i < 4096; i += 256)
            s8[i] = (uint8_t)(gi[i] >> sh);
    }
    __syncthreads();

    // build codebook slice: scb[cl*sz + j], cl = local channel 0..31
    int n = sz << 5;
    for (int u = tid; u < n; u += 256) {
        int cl = u >> L;
        int j  = u & (sz - 1);
        float v = 0.f;
        #pragma unroll 8
        for (int s = 0; s < L; s++) {
            int bit = (j >> (L - 1 - s)) & 1;
            v += srow[sst[2 * s + bit] * 32 + cl];
        }
        scb[u] = v;
    }
    __syncthreads();

    // loss finalize (one CTA; quant complete by stream order)
    if (bid == 0) {
        int l = tid >> 5, ln = tid & 31;
        float s = 0.f;
        #pragma unroll
        for (int k = 0; k < 8; k++) s += g_part[(ln + 32 * k) * 8 + l];
        #pragma unroll
        for (int o = 16; o; o >>= 1) s += __shfl_xor_sync(0xffffffffu, s, o);
        if (ln == 0)
            out[OUT_TENSOR + l] = (c_coef[l] + 0.4f) * s * (1.0f / 8388608.0f);
    }

    // per-thread indices: quad g covers hw = g*1024 + 4*tid .. +3
    int o[16];
    #pragma unroll
    for (int g = 0; g < 4; g++) {
        uint32_t u = sidx[g * 256 + tid];
        o[4 * g + 0] =  u        & 255;
        o[4 * g + 1] = (u >> 8)  & 255;
        o[4 * g + 2] = (u >> 16) & 255;
        o[4 * g + 3] =  u >> 24;
    }

    // out index = ((level*16 + b)*128 + q*32 + cl) * 4096 + hw
    float* ob = out + ((((size_t)((level << 4) + b) << 7) + ((size_t)(q << 5))) << 12)
                    + (tid << 2);
    const float* row = scb;
    for (int cl = 0; cl < 32; cl++) {
        #pragma unroll
        for (int g = 0; g < 4; g++) {
            float4 v = make_float4(row[o[4 * g + 0]], row[o[4 * g + 1]],
                                   row[o[4 * g + 2]], row[o[4 * g + 3]]);
            *reinterpret_cast<float4*>(ob + g * 1024) = v;
        }
        row += sz;
        ob  += 4096;
    }
}

// ---------------------------------------------------------------------------
extern "C" void kernel_launch(void* const* d_in, const int* in_sizes, int n_in,
                              void* d_out, int out_size) {
    const float* inp = (const float*)d_in[0];   // (16,128,64,64) f32
    const float* w   = (const float*)d_in[1];   // (256,128) f32
    float* out       = (float*)d_out;

    (void)in_sizes; (void)n_in; (void)out_size;

    build_kernel<<<510, 128>>>(w);
    quant_kernel<<<256, 256>>>(inp, w);
    scatter_kernel<<<512, 256>>>(w, out);
}

// round 16
// speedup vs baseline: 1.3616x; 1.0390x over previous
#include <cuda_runtime.h>
#include <cstdint>
#include <cstddef>

#define D 128
#define NVEC 65536                 // 16 * 64 * 64
#define OUT_TENSOR 67108864LL      // 8*16*128*64*64

// -------- scratch (static device globals; no runtime allocation) --------
__device__ unsigned long long g_idx[NVEC];   // 8 packed uint8 indices per vector
__device__ float    g_part[256 * 8];         // per-CTA loss partials
__device__ unsigned g_ctr = 0;               // monotonic grid-barrier counter

// stage -> SLOT indices into the packed 10 distinct rows (c_rl order)
__constant__ int c_st[16]   = {0,1, 2,3, 3,4, 4,5, 5,6, 6,7, 7,8, 8,9};
__constant__ int c_rl[10]   = {0, 1, 3, 4, 5, 6, 7, 8, 9, 10};   // distinct rows
__constant__ float c_coef[8] = {1.5f, 1.2f, 1.0f, 0.9f, 0.82f, 0.69f, 0.65f, 0.56f};
// upper-triangular pair list for the 10x10 gram matrix (slot indices)
__constant__ unsigned char c_pi[55] = {0,0,0,0,0,0,0,0,0,0, 1,1,1,1,1,1,1,1,1,
                                       2,2,2,2,2,2,2,2, 3,3,3,3,3,3,3, 4,4,4,4,4,4,
                                       5,5,5,5,5, 6,6,6,6, 7,7,7, 8,8, 9};
__constant__ unsigned char c_pj[55] = {0,1,2,3,4,5,6,7,8,9, 1,2,3,4,5,6,7,8,9,
                                       2,3,4,5,6,7,8,9, 3,4,5,6,7,8,9, 4,5,6,7,8,9,
                                       5,6,7,8,9, 6,7,8,9, 7,8,9, 8,9, 9};

// ---------------------------------------------------------------------------
// ONE fused persistent kernel. 256 CTAs x 256 threads, occ 2 => all CTAs
// resident => device grid barrier is deadlock-free and graph-replay-safe
// (monotonic counter). Phases: prelude (Gram+norms) -> quant -> barrier ->
// scatter (2 tiles per CTA: bid and 511-bid).
// ---------------------------------------------------------------------------
__global__ void __launch_bounds__(256, 2)
fused_kernel(const float* __restrict__ inp, const float* __restrict__ w,
             float* __restrict__ out) {
    __shared__ __align__(16) float s_bv[10][128];   // 10 distinct rows *(-2)
    __shared__ float    sG[100];      // gram of scaled rows (= 4 * true gram)
    __shared__ float    sC[768];      // padded codeword norms
    __shared__ float    s_loss[8];
    __shared__ float    scb[8192];    // scatter: 32 channels x sz (<=256)
    __shared__ float    srow[320];    // scatter: 10 slots x 32 channels
    __shared__ uint32_t sidx[1024];   // scatter: 4096 byte-indices
    __shared__ int      sst[16];

    int tid = threadIdx.x, wid = tid >> 5, lane = tid & 31;
    int bid = blockIdx.x;

    // ---------------- prelude: base rows + Gram + codeword norms ----------
    if (tid < 16) sst[tid] = c_st[tid];
    for (int i = tid; i < 1280; i += 256) {
        int t = i >> 7, c = i & 127;
        s_bv[t][c] = -2.0f * w[c_rl[t] * D + c];
    }
    if (tid < 8) s_loss[tid] = 0.f;
    __syncthreads();

    for (int p = wid; p < 55; p += 8) {
        int i = c_pi[p], j = c_pj[p];
        float s = 0.f;
        #pragma unroll
        for (int cc = 0; cc < 4; cc++)
            s = fmaf(s_bv[i][lane + 32 * cc], s_bv[j][lane + 32 * cc], s);
        #pragma unroll
        for (int o = 16; o; o >>= 1) s += __shfl_xor_sync(0xffffffffu, s, o);
        if (lane == 0) { sG[i * 10 + j] = s; sG[j * 10 + i] = s; }
    }
    __syncthreads();

    // codeword norms via per-thread bit-path recurrence (256 paths)
    {
        const int padv[8] = {0, 4, 8, 16, 48, 112, 240, 496};
        int u[8];
        #pragma unroll
        for (int l = 1; l <= 8; l++) {
            int bit = (tid >> (8 - l)) & 1;
            u[l - 1] = (l == 1) ? bit : (l + bit);
        }
        float M = 0.f;
        #pragma unroll
        for (int l = 1; l <= 8; l++) {
            float cross = 0.f;
            #pragma unroll
            for (int s = 0; s < l - 1; s++) cross += sG[u[s] * 10 + u[l - 1]];
            M += 2.f * cross + sG[u[l - 1] * 10 + u[l - 1]];
            if ((tid & ((1 << (8 - l)) - 1)) == 0)
                sC[padv[l - 1] + (tid >> (8 - l))] = 0.25f * M;
        }
    }
    __syncthreads();

    // ---------------- quant phase (validated R15 body) ---------------------
    int vec = bid * 256 + tid;                            // 0..65535
    const float* xp = inp + ((size_t)(vec >> 12) << 19) + (vec & 4095);
    const float4* sb4 = reinterpret_cast<const float4*>(&s_bv[0][0]);

    float acc[10];
    #pragma unroll
    for (int t = 0; t < 10; t++) acc[t] = 0.f;
    float xn = 0.f;

    #pragma unroll 4
    for (int c4 = 0; c4 < 32; c4++) {
        float x0 = xp[(4 * c4 + 0) * 4096];
        float x1 = xp[(4 * c4 + 1) * 4096];
        float x2 = xp[(4 * c4 + 2) * 4096];
        float x3 = xp[(4 * c4 + 3) * 4096];
        xn = fmaf(x0, x0, xn); xn = fmaf(x1, x1, xn);
        xn = fmaf(x2, x2, xn); xn = fmaf(x3, x3, xn);
        #pragma unroll
        for (int t = 0; t < 10; t++) {
            float4 b = sb4[t * 32 + c4];
            acc[t] = fmaf(x0, b.x, acc[t]);
            acc[t] = fmaf(x1, b.y, acc[t]);
            acc[t] = fmaf(x2, b.z, acc[t]);
            acc[t] = fmaf(x3, b.w, acc[t]);
        }
    }

    // p[2s+b] = -2 x . v_{s,b}  (stage slots: (0,1)(2,3)(3,4)(4,5)(5,6)(6,7)(7,8)(8,9))
    float p[16] = {acc[0], acc[1], acc[2], acc[3], acc[3], acc[4], acc[4], acc[5],
                   acc[5], acc[6], acc[6], acc[7], acc[7], acc[8], acc[8], acc[9]};

    float A2[4], A3[8], A4[16], B2[4], B3[8], B4[16];
    #pragma unroll
    for (int j = 0; j < 4;  j++) A2[j] = p[j >> 1] + p[2 + (j & 1)];
    #pragma unroll
    for (int j = 0; j < 8;  j++) A3[j] = A2[j >> 1] + p[4 + (j & 1)];
    #pragma unroll
    for (int j = 0; j < 16; j++) A4[j] = A3[j >> 1] + p[6 + (j & 1)];
    #pragma unroll
    for (int j = 0; j < 4;  j++) B2[j] = p[8 + (j >> 1)] + p[10 + (j & 1)];
    #pragma unroll
    for (int j = 0; j < 8;  j++) B3[j] = B2[j >> 1] + p[12 + (j & 1)];
    #pragma unroll
    for (int j = 0; j < 16; j++) B4[j] = B3[j >> 1] + p[14 + (j & 1)];

    const float INF = __int_as_float(0x7f800000);
    float m[8]; int mi[8];
    #pragma unroll
    for (int l = 0; l < 8; l++) { m[l] = INF; mi[l] = 0; }

    // strict '<' keeps the FIRST minimum (matches jnp.argmin tie-break)
    #pragma unroll
    for (int j = 0; j < 2;   j++) { float s = p[j]            + sC[0   + j]; if (s < m[0]) { m[0] = s; mi[0] = j; } }
    #pragma unroll
    for (int j = 0; j < 4;   j++) { float s = A2[j]           + sC[4   + j]; if (s < m[1]) { m[1] = s; mi[1] = j; } }
    #pragma unroll
    for (int j = 0; j < 8;   j++) { float s = A3[j]           + sC[8   + j]; if (s < m[2]) { m[2] = s; mi[2] = j; } }
    #pragma unroll
    for (int j = 0; j < 16;  j++) { float s = A4[j]           + sC[16  + j]; if (s < m[3]) { m[3] = s; mi[3] = j; } }
    #pragma unroll
    for (int j = 0; j < 32;  j++) { float s = A4[j >> 1] + p[8 + (j & 1)]  + sC[48  + j]; if (s < m[4]) { m[4] = s; mi[4] = j; } }
    #pragma unroll
    for (int j = 0; j < 64;  j++) { float s = A4[j >> 2] + B2[j & 3]       + sC[112 + j]; if (s < m[5]) { m[5] = s; mi[5] = j; } }
    #pragma unroll
    for (int j = 0; j < 128; j++) { float s = A4[j >> 3] + B3[j & 7]       + sC[240 + j]; if (s < m[6]) { m[6] = s; mi[6] = j; } }
    #pragma unroll
    for (int j = 0; j < 256; j++) { float s = A4[j >> 4] + B4[j & 15]      + sC[496 + j]; if (s < m[7]) { m[7] = s; mi[7] = j; } }

    unsigned long long pk = 0;
    #pragma unroll
    for (int l = 0; l < 8; l++) pk |= ((unsigned long long)(unsigned)mi[l]) << (8 * l);
    g_idx[vec] = pk;

    #pragma unroll
    for (int l = 0; l < 8; l++) {
        float v = xn + m[l];
        #pragma unroll
        for (int o = 16; o; o >>= 1) v += __shfl_xor_sync(0xffffffffu, v, o);
        if (lane == 0) atomicAdd(&s_loss[l], v);
    }
    __syncthreads();
    if (tid < 8) g_part[bid * 8 + tid] = s_loss[tid];
    __syncthreads();

    // ---------------- grid barrier (monotonic, replay-safe) ----------------
    if (tid == 0) {
        __threadfence();
        unsigned old = atomicAdd(&g_ctr, 1u);
        unsigned target = ((old >> 8) + 1u) << 8;     // next multiple of 256
        while (*(volatile unsigned*)&g_ctr < target) { }
        __threadfence();
    }
    __syncthreads();

    // ---------------- loss finalize (CTA 0) --------------------------------
    if (bid == 0) {
        int l = tid >> 5, ln = tid & 31;
        float s = 0.f;
        #pragma unroll
        for (int k = 0; k < 8; k++) s += g_part[(ln + 32 * k) * 8 + l];
        #pragma unroll
        for (int o = 16; o; o >>= 1) s += __shfl_xor_sync(0xffffffffu, s, o);
        if (ln == 0)
            out[OUT_TENSOR + l] = (c_coef[l] + 0.4f) * s * (1.0f / 8388608.0f);
    }

    // ---------------- scatter phase: tiles bid and 511-bid -----------------
    #pragma unroll 1
    for (int pass = 0; pass < 2; pass++) {
        int t     = pass ? (511 - bid) : bid;
        int level = 7 - (t >> 6);        // heavy tile first for pass 0
        int r     = t & 63;
        int b     = r >> 2;              // 0..15
        int q     = r & 3;               // channel quarter
        int L     = level + 1;
        int sz    = 2 << level;

        for (int i = tid; i < 320; i += 256)
            srow[i] = w[c_rl[i >> 5] * D + q * 32 + (i & 31)];
        {
            const unsigned long long* gi = g_idx + ((size_t)b << 12);
            int sh = level << 3;
            uint8_t* s8 = reinterpret_cast<uint8_t*>(sidx);
            for (int i = tid; i < 4096; i += 256)
                s8[i] = (uint8_t)(gi[i] >> sh);
        }
        __syncthreads();

        // build codebook slice: scb[cl*sz + j], cl = local channel 0..31
        int n = sz << 5;
        for (int u = tid; u < n; u += 256) {
            int cl = u >> L;
            int j  = u & (sz - 1);
            float v = 0.f;
            #pragma unroll 8
            for (int s = 0; s < L; s++) {
                int bit = (j >> (L - 1 - s)) & 1;
                v += srow[sst[2 * s + bit] * 32 + cl];
            }
            scb[u] = v;
        }
        __syncthreads();

        // per-thread indices: quad g covers hw = g*1024 + 4*tid .. +3
        int o[16];
        #pragma unroll
        for (int g = 0; g < 4; g++) {
            uint32_t u = sidx[g * 256 + tid];
            o[4 * g + 0] =  u        & 255;
            o[4 * g + 1] = (u >> 8)  & 255;
            o[4 * g + 2] = (u >> 16) & 255;
            o[4 * g + 3] =  u >> 24;
        }

        // out index = ((level*16 + b)*128 + q*32 + cl) * 4096 + hw
        float* ob = out + ((((size_t)((level << 4) + b) << 7) + ((size_t)(q << 5))) << 12)
                        + (tid << 2);
        const float* row = scb;
        for (int cl = 0; cl < 32; cl++) {
            #pragma unroll
            for (int g = 0; g < 4; g++) {
                float4 v = make_float4(row[o[4 * g + 0]], row[o[4 * g + 1]],
                                       row[o[4 * g + 2]], row[o[4 * g + 3]]);
                *reinterpret_cast<float4*>(ob + g * 1024) = v;
            }
            row += sz;
            ob  += 4096;
        }
        __syncthreads();   // protect scb/sidx reuse between passes
    }
}

// ---------------------------------------------------------------------------
extern "C" void kernel_launch(void* const* d_in, const int* in_sizes, int n_in,
                              void* d_out, int out_size) {
    const float* inp = (const float*)d_in[0];   // (16,128,64,64) f32
    const float* w   = (const float*)d_in[1];   // (256,128) f32
    float* out       = (float*)d_out;

    (void)in_sizes; (void)n_in; (void)out_size;

    fused_kernel<<<256, 256>>>(inp, w, out);
}